// round 14
// baseline (speedup 1.0000x reference)
#include <cuda_runtime.h>
#include <cuda_bf16.h>
#include <cstdint>

// Problem constants (fixed by the dataset)
#define NN   50000
#define EE   800000
#define FIN  128
#define HH   4
#define DHH  64
#define HID  256   // HH*DHH

#define NM_A 25088                    // node/row split: A half (196 GEMM row-blocks)
#define NM_B (NN - NM_A)              // 24912
#define YB_A 196
#define YB_FULL 391                   // ceil(50000/128)
#define YB_B (YB_FULL - YB_A)         // 195

// ---------------- static device scratch ----------------
__device__ float    g_feat0[(size_t)NN * HID];
__device__ float    g_feat1[(size_t)NN * HID];
__device__ float    g_res [(size_t)NN * HID];
__device__ float    g_h1  [(size_t)NN * HID];
__device__ float    g_h2  [(size_t)NN * HID];
__device__ float    g_el0 [(size_t)NN * HH], g_er0[(size_t)NN * HH];
__device__ float    g_el1 [(size_t)NN * HH], g_er1[(size_t)NN * HH];
__device__ unsigned g_gmax[24];                      // 3 layers x (el[0..3], er[4..7])
__device__ unsigned g_B0h[(size_t)HID / 2 * HID], g_B0l[(size_t)HID / 2 * HID];
__device__ unsigned g_B1h[(size_t)HID / 2 * HID], g_B1l[(size_t)HID / 2 * HID];
__device__ unsigned g_B2h[(size_t)HID / 2 * HID], g_B2l[(size_t)HID / 2 * HID];
__device__ unsigned g_Brh[(size_t)HID / 2 * HID], g_Brl[(size_t)HID / 2 * HID];
__device__ int      g_deg   [NN];
__device__ int      g_rowptr[NN + 1];
__device__ int      g_cursor[NN];
__device__ int      g_esrc  [EE];

__device__ __forceinline__ unsigned enc_f(float v) {
    unsigned b = __float_as_uint(v);
    return (b & 0x80000000u) ? ~b : (b | 0x80000000u);
}
__device__ __forceinline__ float dec_f(unsigned u) {
    unsigned b = (u & 0x80000000u) ? (u ^ 0x80000000u) : ~u;
    return __uint_as_float(b);
}
__device__ __forceinline__ unsigned pack_bf16(float a, float b) {
    unsigned r;
    asm("cvt.rn.bf16x2.f32 %0, %1, %2;" : "=r"(r) : "f"(b), "f"(a));
    return r;
}
__device__ __forceinline__ float bf16_hi_f(float w) {
    return __bfloat162float(__float2bfloat16(w));
}

// ============ B pre-conversion: W[K,N] fp32 -> packed bf16 hi/lo pairs along K ============
__global__ void convW_k(const float* __restrict__ W, unsigned* __restrict__ Bh,
                        unsigned* __restrict__ Bl, int K2, int N)
{
    int i = blockIdx.x * blockDim.x + threadIdx.x;
    if (i >= K2 * N) return;
    int k2 = i / N, n = i - k2 * N;
    float w0 = W[(size_t)(2 * k2) * N + n];
    float w1 = W[(size_t)(2 * k2 + 1) * N + n];
    float h0 = bf16_hi_f(w0), h1 = bf16_hi_f(w1);
    Bh[i] = pack_bf16(h0, h1);
    Bl[i] = pack_bf16(w0 - h0, w1 - h1);
}

// ===== GEMM: C = A @ B via 3xBF16 m16n8k16, double-buffered; fused el/er + gmax =====
#define MMA_BF16(d, a, b0, b1)                                               \
    asm volatile("mma.sync.aligned.m16n8k16.row.col.f32.bf16.bf16.f32 "      \
                 "{%0,%1,%2,%3}, {%4,%5,%6,%7}, {%8,%9}, {%0,%1,%2,%3};"     \
                 : "+f"(d[0]), "+f"(d[1]), "+f"(d[2]), "+f"(d[3])            \
                 : "r"(a[0]), "r"(a[1]), "r"(a[2]), "r"(a[3]),               \
                   "r"(b0), "r"(b1))

#define BM 128
#define BN 64
#define BK 16
#define APAD 12
#define BPAD 72

template<bool FUSE>
__global__ void __launch_bounds__(128) gemm_bf16x3(
    const float* __restrict__ A,
    const unsigned* __restrict__ Bhg, const unsigned* __restrict__ Blg,
    float* __restrict__ C,
    const float* __restrict__ al, const float* __restrict__ ar,
    float* __restrict__ el, float* __restrict__ er, unsigned* __restrict__ gmax,
    int M, int K, int N, int yoff)
{
    __shared__ unsigned Ah[2][BM * APAD], Al[2][BM * APAD];
    __shared__ unsigned Bh[2][8 * BPAD], Bl[2][8 * BPAD];

    const int tid  = threadIdx.x;
    const int lane = tid & 31;
    const int wid  = tid >> 5;
    const int rowBase = (blockIdx.y + yoff) * BM;
    const int colBase = blockIdx.x * BN;

    float c[2][8][4];
#pragma unroll
    for (int mt = 0; mt < 2; mt++)
#pragma unroll
        for (int nt = 0; nt < 8; nt++)
#pragma unroll
            for (int i = 0; i < 4; i++) c[mt][nt][i] = 0.f;

    float4 av[4];
    uint4  bhv, blv;

    const int aRow  = tid >> 2;
    const int aCol4 = (tid & 3) << 2;
    const int bR    = tid >> 4;
    const int bC4   = (tid & 15) << 2;

    auto ldgA = [&](int kt) {
#pragma unroll
        for (int i = 0; i < 4; i++) {
            int gr = rowBase + aRow + 32 * i;
            av[i] = (gr < M) ? *(const float4*)(A + (size_t)gr * K + kt + aCol4)
                             : make_float4(0.f, 0.f, 0.f, 0.f);
        }
    };
    auto ldgB = [&](int kt) {
        size_t off = (size_t)(kt / 2 + bR) * N + colBase + bC4;
        bhv = *(const uint4*)(Bhg + off);
        blv = *(const uint4*)(Blg + off);
    };
    auto stsAB = [&](int buf) {
#pragma unroll
        for (int i = 0; i < 4; i++) {
            float hx = bf16_hi_f(av[i].x), hy = bf16_hi_f(av[i].y);
            float hz = bf16_hi_f(av[i].z), hw = bf16_hi_f(av[i].w);
            int idx = (aRow + 32 * i) * APAD + (aCol4 >> 1);
            *(uint2*)&Ah[buf][idx] = make_uint2(pack_bf16(hx, hy), pack_bf16(hz, hw));
            *(uint2*)&Al[buf][idx] = make_uint2(pack_bf16(av[i].x - hx, av[i].y - hy),
                                                pack_bf16(av[i].z - hz, av[i].w - hw));
        }
        int bidx = bR * BPAD + bC4;
        *(uint4*)&Bh[buf][bidx] = bhv;
        *(uint4*)&Bl[buf][bidx] = blv;
    };

    ldgA(0); ldgB(0);
    stsAB(0);
    __syncthreads();

    const int ntiles = K / BK;
    for (int t = 0; t < ntiles; t++) {
        const int buf = t & 1;
        if (t + 1 < ntiles) { ldgA((t + 1) * BK); ldgB((t + 1) * BK); }

        unsigned ah[2][4], alr[2][4];
#pragma unroll
        for (int mt = 0; mt < 2; mt++) {
            int r  = wid * 32 + mt * 16 + (lane >> 2);
            int c0 = lane & 3;
            ah [mt][0] = Ah[buf][r * APAD + c0];
            ah [mt][1] = Ah[buf][(r + 8) * APAD + c0];
            ah [mt][2] = Ah[buf][r * APAD + c0 + 4];
            ah [mt][3] = Ah[buf][(r + 8) * APAD + c0 + 4];
            alr[mt][0] = Al[buf][r * APAD + c0];
            alr[mt][1] = Al[buf][(r + 8) * APAD + c0];
            alr[mt][2] = Al[buf][r * APAD + c0 + 4];
            alr[mt][3] = Al[buf][(r + 8) * APAD + c0 + 4];
        }
#pragma unroll
        for (int nt = 0; nt < 8; nt++) {
            int col = nt * 8 + (lane >> 2);
            int kr  = lane & 3;
            unsigned bh0 = Bh[buf][kr * BPAD + col], bh1 = Bh[buf][(kr + 4) * BPAD + col];
            unsigned bl0 = Bl[buf][kr * BPAD + col], bl1 = Bl[buf][(kr + 4) * BPAD + col];
#pragma unroll
            for (int mt = 0; mt < 2; mt++) {
                MMA_BF16(c[mt][nt], ah[mt],  bh0, bh1);
                MMA_BF16(c[mt][nt], alr[mt], bh0, bh1);
                MMA_BF16(c[mt][nt], ah[mt],  bl0, bl1);
            }
        }
        if (t + 1 < ntiles) stsAB(buf ^ 1);
        __syncthreads();
    }

    // ---- store C ----
#pragma unroll
    for (int mt = 0; mt < 2; mt++) {
        int r0 = rowBase + wid * 32 + mt * 16 + (lane >> 2);
        int r1 = r0 + 8;
#pragma unroll
        for (int nt = 0; nt < 8; nt++) {
            int cc = colBase + nt * 8 + (lane & 3) * 2;
            if (r0 < M) *(float2*)(C + (size_t)r0 * N + cc) = make_float2(c[mt][nt][0], c[mt][nt][1]);
            if (r1 < M) *(float2*)(C + (size_t)r1 * N + cc) = make_float2(c[mt][nt][2], c[mt][nt][3]);
        }
    }

    // ---- fused el/er + per-head global max: this col-block is head h = blockIdx.x ----
    if (FUSE) {
        int h = blockIdx.x;
        float alv[16], arv[16];
#pragma unroll
        for (int nt = 0; nt < 8; nt++)
#pragma unroll
            for (int j = 0; j < 2; j++) {
                int cc = nt * 8 + (lane & 3) * 2 + j;
                alv[nt * 2 + j] = al[h * 64 + cc];
                arv[nt * 2 + j] = ar[h * 64 + cc];
            }
        float mel = -1e30f, mer = -1e30f;
#pragma unroll
        for (int mt = 0; mt < 2; mt++) {
            float e0 = 0, e1 = 0, f0 = 0, f1 = 0;
#pragma unroll
            for (int nt = 0; nt < 8; nt++)
#pragma unroll
                for (int j = 0; j < 2; j++) {
                    e0 += c[mt][nt][j]     * alv[nt * 2 + j];
                    e1 += c[mt][nt][2 + j] * alv[nt * 2 + j];
                    f0 += c[mt][nt][j]     * arv[nt * 2 + j];
                    f1 += c[mt][nt][2 + j] * arv[nt * 2 + j];
                }
#pragma unroll
            for (int off = 1; off < 4; off <<= 1) {
                e0 += __shfl_xor_sync(0xffffffffu, e0, off);
                e1 += __shfl_xor_sync(0xffffffffu, e1, off);
                f0 += __shfl_xor_sync(0xffffffffu, f0, off);
                f1 += __shfl_xor_sync(0xffffffffu, f1, off);
            }
            mel = fmaxf(mel, fmaxf(e0, e1));
            mer = fmaxf(mer, fmaxf(f0, f1));
            if ((lane & 3) == 0) {
                int r0 = rowBase + wid * 32 + mt * 16 + (lane >> 2);
                int r1 = r0 + 8;
                if (r0 < M) { el[(size_t)r0 * HH + h] = e0; er[(size_t)r0 * HH + h] = f0; }
                if (r1 < M) { el[(size_t)r1 * HH + h] = e1; er[(size_t)r1 * HH + h] = f1; }
            }
        }
        // warp max over the 8 row groups, then one atomic per warp per slot
#pragma unroll
        for (int off = 4; off < 32; off <<= 1) {
            mel = fmaxf(mel, __shfl_xor_sync(0xffffffffu, mel, off));
            mer = fmaxf(mer, __shfl_xor_sync(0xffffffffu, mer, off));
        }
        if (lane == 0) {
            atomicMax(&gmax[h],     enc_f(mel));
            atomicMax(&gmax[4 + h], enc_f(mer));
        }
    }
}

// ================= CSR build (once; edges shared by all layers) =================
__global__ void hist_k(const int* __restrict__ dst, int* deg, int E)
{
    int i = blockIdx.x * blockDim.x + threadIdx.x;
    if (i < E) atomicAdd(&deg[dst[i]], 1);
}

__global__ void scan_k(const int* __restrict__ deg, int* __restrict__ rowptr,
                       int* __restrict__ cursor, int n, int E)
{
    const int C = (n + 1023) >> 10;
    int t = threadIdx.x;
    int base = t * C;
    int s = 0;
    for (int i = 0; i < C; i++) { int id = base + i; if (id < n) s += deg[id]; }
    __shared__ int sm[1024];
    sm[t] = s;
    __syncthreads();
    for (int off = 1; off < 1024; off <<= 1) {
        int v = (t >= off) ? sm[t - off] : 0;
        __syncthreads();
        sm[t] += v;
        __syncthreads();
    }
    int run = sm[t] - s;
    for (int i = 0; i < C; i++) {
        int id = base + i;
        if (id < n) { rowptr[id] = run; cursor[id] = run; run += deg[id]; }
    }
    if (t == 0) rowptr[n] = E;
}

__global__ void scatter_k(const int* __restrict__ src, const int* __restrict__ dst,
                          int* cursor, int* __restrict__ esrc, int E)
{
    int i = blockIdx.x * blockDim.x + threadIdx.x;
    if (i >= E) return;
    int p = atomicAdd(&cursor[dst[i]], 1);
    esrc[p] = src[i];
}

// ================= GAT aggregation: 2 warps per node, 1 float4/lane; node range =================
template<int MODE>
__global__ void __launch_bounds__(256) gat_node_k(
    const float4* __restrict__ feat4,
    const int* __restrict__ rowptr, const int* __restrict__ esrc,
    const float* __restrict__ el, const float* __restrict__ er,
    const unsigned* __restrict__ gmax,
    const float4* __restrict__ res4, const float4* __restrict__ bias4,
    float* __restrict__ out, int nodeOff, int nodeCnt)
{
    __shared__ float smv[4][64];
    int w    = threadIdx.x >> 5;
    int lane = threadIdx.x & 31;
    int gw   = blockIdx.x * 8 + w;
    int ln   = gw >> 1;
    int node = nodeOff + ln;
    int half = gw & 1;
    bool active = (ln < nodeCnt);

    float4 v = make_float4(0.f, 0.f, 0.f, 0.f);
    int colf = half * 32 + lane;
    int h    = colf >> 4;

    if (active) {
        int start = rowptr[node], end = rowptr[node + 1];
        float m   = dec_f(gmax[h]) + dec_f(gmax[4 + h]);
        float erB = er[(size_t)node * HH + h];

        float4 acc = make_float4(0.f, 0.f, 0.f, 0.f);
        float den = 0.f;
        int idx = start;
        for (; idx + 4 <= end; idx += 4) {
            int s0 = esrc[idx], s1 = esrc[idx + 1], s2 = esrc[idx + 2], s3 = esrc[idx + 3];
            float e0 = el[(size_t)s0 * HH + h];
            float e1 = el[(size_t)s1 * HH + h];
            float e2 = el[(size_t)s2 * HH + h];
            float e3 = el[(size_t)s3 * HH + h];
            float4 f0 = feat4[(size_t)s0 * 64 + colf];
            float4 f1 = feat4[(size_t)s1 * 64 + colf];
            float4 f2 = feat4[(size_t)s2 * 64 + colf];
            float4 f3 = feat4[(size_t)s3 * 64 + colf];
            float v0 = e0 + erB; v0 = v0 > 0.f ? v0 : 0.2f * v0;
            float v1 = e1 + erB; v1 = v1 > 0.f ? v1 : 0.2f * v1;
            float v2 = e2 + erB; v2 = v2 > 0.f ? v2 : 0.2f * v2;
            float v3 = e3 + erB; v3 = v3 > 0.f ? v3 : 0.2f * v3;
            float w0 = __expf(v0 - m), w1 = __expf(v1 - m);
            float w2 = __expf(v2 - m), w3 = __expf(v3 - m);
            den += (w0 + w1) + (w2 + w3);
            acc.x += w0 * f0.x + w1 * f1.x + w2 * f2.x + w3 * f3.x;
            acc.y += w0 * f0.y + w1 * f1.y + w2 * f2.y + w3 * f3.y;
            acc.z += w0 * f0.z + w1 * f1.z + w2 * f2.z + w3 * f3.z;
            acc.w += w0 * f0.w + w1 * f1.w + w2 * f2.w + w3 * f3.w;
        }
        for (; idx < end; idx++) {
            int s0 = esrc[idx];
            float e0 = el[(size_t)s0 * HH + h];
            float4 f0 = feat4[(size_t)s0 * 64 + colf];
            float v0 = e0 + erB; v0 = v0 > 0.f ? v0 : 0.2f * v0;
            float w0 = __expf(v0 - m);
            den += w0;
            acc.x += w0 * f0.x; acc.y += w0 * f0.y;
            acc.z += w0 * f0.z; acc.w += w0 * f0.w;
        }
        float inv = 1.f / fmaxf(den, 1e-16f);
        float4 r = res4[(size_t)node * 64 + colf];
        float4 b = bias4[colf];
        v.x = acc.x * inv + r.x + b.x;
        v.y = acc.y * inv + r.y + b.y;
        v.z = acc.z * inv + r.z + b.z;
        v.w = acc.w * inv + r.w + b.w;
    }

    if (MODE == 0) {
        if (active) {
            float4* o4 = (float4*)out + (size_t)node * 64 + colf;
            *o4 = make_float4(fmaxf(v.x, 0.f), fmaxf(v.y, 0.f), fmaxf(v.z, 0.f), fmaxf(v.w, 0.f));
        }
    } else {
        if (active) {
            v.x += __shfl_xor_sync(0xffffffffu, v.x, 16);
            v.y += __shfl_xor_sync(0xffffffffu, v.y, 16);
            v.z += __shfl_xor_sync(0xffffffffu, v.z, 16);
            v.w += __shfl_xor_sync(0xffffffffu, v.w, 16);
            if (half == 1 && lane < 16) *(float4*)&smv[w >> 1][lane * 4] = v;
        }
        __syncthreads();
        if (active && half == 0 && lane < 16) {
            float4 o = *(const float4*)&smv[w >> 1][lane * 4];
            float4 y = make_float4((v.x + o.x) * 0.25f, (v.y + o.y) * 0.25f,
                                   (v.z + o.z) * 0.25f, (v.w + o.w) * 0.25f);
            *((float4*)out + (size_t)node * 16 + lane) = y;
        }
    }
}

// ================= host orchestration (pipelined multi-stream DAG) =================
extern "C" void kernel_launch(void* const* d_in, const int* in_sizes, int n_in,
                              void* d_out, int out_size)
{
    const float* x  = (const float*)d_in[0];
    const int*   ei = (const int*)d_in[1];
    const int E  = in_sizes[1] / 2;
    const int Nn = in_sizes[0] / FIN;
    const int* src = ei;
    const int* dst = ei + E;
    const float* W[3]  = {(const float*)d_in[2],  (const float*)d_in[3],  (const float*)d_in[4]};
    const float* al[3] = {(const float*)d_in[5],  (const float*)d_in[6],  (const float*)d_in[7]};
    const float* ar[3] = {(const float*)d_in[8],  (const float*)d_in[9],  (const float*)d_in[10]};
    const float* bb[3] = {(const float*)d_in[11], (const float*)d_in[12], (const float*)d_in[13]};
    const float* resW0 = (const float*)d_in[14];

    float *feat0, *feat1, *res, *h1, *h2, *el0, *er0, *el1, *er1;
    unsigned *gmax;
    unsigned *B0h, *B0l, *B1h, *B1l, *B2h, *B2l, *Brh, *Brl;
    int *deg, *rowptr, *cursor, *esrc;
    cudaGetSymbolAddress((void**)&feat0,  g_feat0);
    cudaGetSymbolAddress((void**)&feat1,  g_feat1);
    cudaGetSymbolAddress((void**)&res,    g_res);
    cudaGetSymbolAddress((void**)&h1,     g_h1);
    cudaGetSymbolAddress((void**)&h2,     g_h2);
    cudaGetSymbolAddress((void**)&el0,    g_el0);
    cudaGetSymbolAddress((void**)&er0,    g_er0);
    cudaGetSymbolAddress((void**)&el1,    g_el1);
    cudaGetSymbolAddress((void**)&er1,    g_er1);
    cudaGetSymbolAddress((void**)&gmax,   g_gmax);
    cudaGetSymbolAddress((void**)&B0h,    g_B0h);
    cudaGetSymbolAddress((void**)&B0l,    g_B0l);
    cudaGetSymbolAddress((void**)&B1h,    g_B1h);
    cudaGetSymbolAddress((void**)&B1l,    g_B1l);
    cudaGetSymbolAddress((void**)&B2h,    g_B2h);
    cudaGetSymbolAddress((void**)&B2l,    g_B2l);
    cudaGetSymbolAddress((void**)&Brh,    g_Brh);
    cudaGetSymbolAddress((void**)&Brl,    g_Brl);
    cudaGetSymbolAddress((void**)&deg,    g_deg);
    cudaGetSymbolAddress((void**)&rowptr, g_rowptr);
    cudaGetSymbolAddress((void**)&cursor, g_cursor);
    cudaGetSymbolAddress((void**)&esrc,   g_esrc);

    static cudaStream_t s1 = nullptr, s2 = nullptr, s3 = nullptr;
    static cudaEvent_t evRoot = nullptr, evCSR = nullptr, evRes = nullptr, evW12 = nullptr;
    static cudaEvent_t evGA0 = nullptr, evG1A = nullptr, evGA1 = nullptr, evG2A = nullptr;
    if (!s1) {
        cudaStreamCreateWithFlags(&s1, cudaStreamNonBlocking);
        cudaStreamCreateWithFlags(&s2, cudaStreamNonBlocking);
        cudaStreamCreateWithFlags(&s3, cudaStreamNonBlocking);
        cudaEventCreateWithFlags(&evRoot, cudaEventDisableTiming);
        cudaEventCreateWithFlags(&evCSR,  cudaEventDisableTiming);
        cudaEventCreateWithFlags(&evRes,  cudaEventDisableTiming);
        cudaEventCreateWithFlags(&evW12,  cudaEventDisableTiming);
        cudaEventCreateWithFlags(&evGA0,  cudaEventDisableTiming);
        cudaEventCreateWithFlags(&evG1A,  cudaEventDisableTiming);
        cudaEventCreateWithFlags(&evGA1,  cudaEventDisableTiming);
        cudaEventCreateWithFlags(&evG2A,  cudaEventDisableTiming);
    }

    const dim3 gridFull(HID / BN, YB_FULL);
    const dim3 gridA(HID / BN, YB_A);
    const dim3 gridB(HID / BN, YB_B);
    const int gatGridA = (2 * NM_A + 7) / 8;
    const int gatGridB = (2 * NM_B + 7) / 8;
    const int gatGridF = (2 * Nn + 7) / 8;

    // ---- root: clear gmax slots + degree histogram; fork ----
    cudaMemsetAsync(gmax, 0, 24 * sizeof(unsigned), 0);
    cudaMemsetAsync(deg, 0, (size_t)Nn * sizeof(int), 0);
    cudaEventRecord(evRoot, 0);

    // ---- s1: CSR chain ----
    cudaStreamWaitEvent(s1, evRoot, 0);
    hist_k<<<(E + 255) / 256, 256, 0, s1>>>(dst, deg, E);
    scan_k<<<1, 1024, 0, s1>>>(deg, rowptr, cursor, Nn, E);
    scatter_k<<<(E + 255) / 256, 256, 0, s1>>>(src, dst, cursor, esrc, E);
    cudaEventRecord(evCSR, s1);

    // ---- s2: residual projection ----
    cudaStreamWaitEvent(s2, evRoot, 0);
    convW_k<<<(FIN / 2 * HID + 255) / 256, 256, 0, s2>>>(resW0, Brh, Brl, FIN / 2, HID);
    gemm_bf16x3<false><<<gridFull, 128, 0, s2>>>(x, Brh, Brl, res,
        nullptr, nullptr, nullptr, nullptr, nullptr, Nn, FIN, HID, 0);
    cudaEventRecord(evRes, s2);

    // ---- s3: W1/W2 conversions ----
    cudaStreamWaitEvent(s3, evRoot, 0);
    convW_k<<<(HID / 2 * HID + 255) / 256, 256, 0, s3>>>(W[1], B1h, B1l, HID / 2, HID);
    convW_k<<<(HID / 2 * HID + 255) / 256, 256, 0, s3>>>(W[2], B2h, B2l, HID / 2, HID);
    cudaEventRecord(evW12, s3);

    // ================= Layer 0 (feat buf0, el0/er0, gmax+0) =================
    convW_k<<<(FIN / 2 * HID + 255) / 256, 256>>>(W[0], B0h, B0l, FIN / 2, HID);
    gemm_bf16x3<true><<<gridFull, 128>>>(x, B0h, B0l, feat0,
        al[0], ar[0], el0, er0, gmax + 0, Nn, FIN, HID, 0);
    cudaStreamWaitEvent(0, evCSR, 0);
    cudaStreamWaitEvent(0, evRes, 0);
    gat_node_k<0><<<gatGridA, 256>>>((const float4*)feat0, rowptr, esrc, el0, er0, gmax + 0,
                                     (const float4*)res, (const float4*)bb[0], h1, 0, NM_A);
    cudaEventRecord(evGA0, 0);
    gat_node_k<0><<<gatGridB, 256>>>((const float4*)feat0, rowptr, esrc, el0, er0, gmax + 0,
                                     (const float4*)res, (const float4*)bb[0], h1, NM_A, NM_B);

    // ---- s2: gemm1(A) overlaps gat0(B) — writes feat1/el1/er1 (no aliasing with layer-0 bufs) ----
    cudaStreamWaitEvent(s2, evGA0, 0);
    cudaStreamWaitEvent(s2, evW12, 0);
    gemm_bf16x3<true><<<gridA, 128, 0, s2>>>(h1, B1h, B1l, feat1,
        al[1], ar[1], el1, er1, gmax + 8, Nn, HID, HID, 0);
    cudaEventRecord(evG1A, s2);

    // ================= Layer 1 (feat buf1, el1/er1, gmax+8) =================
    gemm_bf16x3<true><<<gridB, 128>>>(h1, B1h, B1l, feat1,
        al[1], ar[1], el1, er1, gmax + 8, Nn, HID, HID, YB_A);
    cudaStreamWaitEvent(0, evG1A, 0);
    gat_node_k<0><<<gatGridA, 256>>>((const float4*)feat1, rowptr, esrc, el1, er1, gmax + 8,
                                     (const float4*)h1, (const float4*)bb[1], h2, 0, NM_A);
    cudaEventRecord(evGA1, 0);
    gat_node_k<0><<<gatGridB, 256>>>((const float4*)feat1, rowptr, esrc, el1, er1, gmax + 8,
                                     (const float4*)h1, (const float4*)bb[1], h2, NM_A, NM_B);

    // ---- s2: gemm2(A) overlaps gat1(B) — writes feat0/el0/er0 (layer-0 values dead) ----
    cudaStreamWaitEvent(s2, evGA1, 0);
    gemm_bf16x3<true><<<gridA, 128, 0, s2>>>(h2, B2h, B2l, feat0,
        al[2], ar[2], el0, er0, gmax + 16, Nn, HID, HID, 0);
    cudaEventRecord(evG2A, s2);

    // ================= Layer 2 (feat buf0, el0/er0, gmax+16) =================
    gemm_bf16x3<true><<<gridB, 128>>>(h2, B2h, B2l, feat0,
        al[2], ar[2], el0, er0, gmax + 16, Nn, HID, HID, YB_A);
    cudaStreamWaitEvent(0, evG2A, 0);
    gat_node_k<2><<<gatGridF, 256>>>((const float4*)feat0, rowptr, esrc, el0, er0, gmax + 16,
                                     (const float4*)h2, (const float4*)bb[2], (float*)d_out, 0, Nn);
}

// round 15
// speedup vs baseline: 1.1088x; 1.1088x over previous
#include <cuda_runtime.h>
#include <cuda_bf16.h>
#include <cstdint>

// Problem constants (fixed by the dataset)
#define NN   50000
#define EE   800000
#define FIN  128
#define HH   4
#define DHH  64
#define HID  256   // HH*DHH

// ---------------- static device scratch ----------------
__device__ float    g_feat[(size_t)NN * HID];
__device__ float    g_res [(size_t)NN * HID];
__device__ float    g_h1  [(size_t)NN * HID];
__device__ float    g_h2  [(size_t)NN * HID];
__device__ float    g_el  [(size_t)NN * HH];
__device__ float    g_er  [(size_t)NN * HH];
__device__ unsigned g_gmax[24];                      // 3 layers x (el[0..3], er[4..7])
__device__ unsigned g_B0h[(size_t)HID / 2 * HID], g_B0l[(size_t)HID / 2 * HID];
__device__ unsigned g_B1h[(size_t)HID / 2 * HID], g_B1l[(size_t)HID / 2 * HID];
__device__ unsigned g_B2h[(size_t)HID / 2 * HID], g_B2l[(size_t)HID / 2 * HID];
__device__ unsigned g_Brh[(size_t)HID / 2 * HID], g_Brl[(size_t)HID / 2 * HID];
__device__ int      g_deg   [NN];
__device__ int      g_rowptr[NN + 1];
__device__ int      g_cursor[NN];
__device__ int      g_esrc  [EE];

__device__ __forceinline__ unsigned enc_f(float v) {
    unsigned b = __float_as_uint(v);
    return (b & 0x80000000u) ? ~b : (b | 0x80000000u);
}
__device__ __forceinline__ float dec_f(unsigned u) {
    unsigned b = (u & 0x80000000u) ? (u ^ 0x80000000u) : ~u;
    return __uint_as_float(b);
}
__device__ __forceinline__ unsigned pack_bf16(float a, float b) {
    unsigned r;
    asm("cvt.rn.bf16x2.f32 %0, %1, %2;" : "=r"(r) : "f"(b), "f"(a));
    return r;
}
__device__ __forceinline__ float bf16_hi_f(float w) {
    return __bfloat162float(__float2bfloat16(w));
}

// ============ B pre-conversion: W[K,N] fp32 -> packed bf16 hi/lo pairs along K ============
__global__ void convW_k(const float* __restrict__ W, unsigned* __restrict__ Bh,
                        unsigned* __restrict__ Bl, int K2, int N)
{
    int i = blockIdx.x * blockDim.x + threadIdx.x;
    if (i >= K2 * N) return;
    int k2 = i / N, n = i - k2 * N;
    float w0 = W[(size_t)(2 * k2) * N + n];
    float w1 = W[(size_t)(2 * k2 + 1) * N + n];
    float h0 = bf16_hi_f(w0), h1 = bf16_hi_f(w1);
    Bh[i] = pack_bf16(h0, h1);
    Bl[i] = pack_bf16(w0 - h0, w1 - h1);
}

// ===== GEMM: C = A @ B via 3xBF16 m16n8k16, double-buffered; fused el/er + gmax =====
#define MMA_BF16(d, a, b0, b1)                                               \
    asm volatile("mma.sync.aligned.m16n8k16.row.col.f32.bf16.bf16.f32 "      \
                 "{%0,%1,%2,%3}, {%4,%5,%6,%7}, {%8,%9}, {%0,%1,%2,%3};"     \
                 : "+f"(d[0]), "+f"(d[1]), "+f"(d[2]), "+f"(d[3])            \
                 : "r"(a[0]), "r"(a[1]), "r"(a[2]), "r"(a[3]),               \
                   "r"(b0), "r"(b1))

#define BM 128
#define BN 64
#define BK 16
#define APAD 12
#define BPAD 72

template<bool FUSE>
__global__ void __launch_bounds__(128) gemm_bf16x3(
    const float* __restrict__ A,
    const unsigned* __restrict__ Bhg, const unsigned* __restrict__ Blg,
    float* __restrict__ C,
    const float* __restrict__ al, const float* __restrict__ ar,
    float* __restrict__ el, float* __restrict__ er, unsigned* __restrict__ gmax,
    int M, int K, int N)
{
    __shared__ unsigned Ah[2][BM * APAD], Al[2][BM * APAD];
    __shared__ unsigned Bh[2][8 * BPAD], Bl[2][8 * BPAD];

    const int tid  = threadIdx.x;
    const int lane = tid & 31;
    const int wid  = tid >> 5;
    const int rowBase = blockIdx.y * BM;
    const int colBase = blockIdx.x * BN;

    float c[2][8][4];
#pragma unroll
    for (int mt = 0; mt < 2; mt++)
#pragma unroll
        for (int nt = 0; nt < 8; nt++)
#pragma unroll
            for (int i = 0; i < 4; i++) c[mt][nt][i] = 0.f;

    float4 av[4];
    uint4  bhv, blv;

    const int aRow  = tid >> 2;
    const int aCol4 = (tid & 3) << 2;
    const int bR    = tid >> 4;
    const int bC4   = (tid & 15) << 2;

    auto ldgA = [&](int kt) {
#pragma unroll
        for (int i = 0; i < 4; i++) {
            int gr = rowBase + aRow + 32 * i;
            av[i] = (gr < M) ? *(const float4*)(A + (size_t)gr * K + kt + aCol4)
                             : make_float4(0.f, 0.f, 0.f, 0.f);
        }
    };
    auto ldgB = [&](int kt) {
        size_t off = (size_t)(kt / 2 + bR) * N + colBase + bC4;
        bhv = *(const uint4*)(Bhg + off);
        blv = *(const uint4*)(Blg + off);
    };
    auto stsAB = [&](int buf) {
#pragma unroll
        for (int i = 0; i < 4; i++) {
            float hx = bf16_hi_f(av[i].x), hy = bf16_hi_f(av[i].y);
            float hz = bf16_hi_f(av[i].z), hw = bf16_hi_f(av[i].w);
            int idx = (aRow + 32 * i) * APAD + (aCol4 >> 1);
            *(uint2*)&Ah[buf][idx] = make_uint2(pack_bf16(hx, hy), pack_bf16(hz, hw));
            *(uint2*)&Al[buf][idx] = make_uint2(pack_bf16(av[i].x - hx, av[i].y - hy),
                                                pack_bf16(av[i].z - hz, av[i].w - hw));
        }
        int bidx = bR * BPAD + bC4;
        *(uint4*)&Bh[buf][bidx] = bhv;
        *(uint4*)&Bl[buf][bidx] = blv;
    };

    ldgA(0); ldgB(0);
    stsAB(0);
    __syncthreads();

    const int ntiles = K / BK;
    for (int t = 0; t < ntiles; t++) {
        const int buf = t & 1;
        if (t + 1 < ntiles) { ldgA((t + 1) * BK); ldgB((t + 1) * BK); }

        unsigned ah[2][4], alr[2][4];
#pragma unroll
        for (int mt = 0; mt < 2; mt++) {
            int r  = wid * 32 + mt * 16 + (lane >> 2);
            int c0 = lane & 3;
            ah [mt][0] = Ah[buf][r * APAD + c0];
            ah [mt][1] = Ah[buf][(r + 8) * APAD + c0];
            ah [mt][2] = Ah[buf][r * APAD + c0 + 4];
            ah [mt][3] = Ah[buf][(r + 8) * APAD + c0 + 4];
            alr[mt][0] = Al[buf][r * APAD + c0];
            alr[mt][1] = Al[buf][(r + 8) * APAD + c0];
            alr[mt][2] = Al[buf][r * APAD + c0 + 4];
            alr[mt][3] = Al[buf][(r + 8) * APAD + c0 + 4];
        }
#pragma unroll
        for (int nt = 0; nt < 8; nt++) {
            int col = nt * 8 + (lane >> 2);
            int kr  = lane & 3;
            unsigned bh0 = Bh[buf][kr * BPAD + col], bh1 = Bh[buf][(kr + 4) * BPAD + col];
            unsigned bl0 = Bl[buf][kr * BPAD + col], bl1 = Bl[buf][(kr + 4) * BPAD + col];
#pragma unroll
            for (int mt = 0; mt < 2; mt++) {
                MMA_BF16(c[mt][nt], ah[mt],  bh0, bh1);
                MMA_BF16(c[mt][nt], alr[mt], bh0, bh1);
                MMA_BF16(c[mt][nt], ah[mt],  bl0, bl1);
            }
        }
        if (t + 1 < ntiles) stsAB(buf ^ 1);
        __syncthreads();
    }

    // ---- store C ----
#pragma unroll
    for (int mt = 0; mt < 2; mt++) {
        int r0 = rowBase + wid * 32 + mt * 16 + (lane >> 2);
        int r1 = r0 + 8;
#pragma unroll
        for (int nt = 0; nt < 8; nt++) {
            int cc = colBase + nt * 8 + (lane & 3) * 2;
            if (r0 < M) *(float2*)(C + (size_t)r0 * N + cc) = make_float2(c[mt][nt][0], c[mt][nt][1]);
            if (r1 < M) *(float2*)(C + (size_t)r1 * N + cc) = make_float2(c[mt][nt][2], c[mt][nt][3]);
        }
    }

    // ---- fused el/er + per-head global max: this col-block is head h = blockIdx.x ----
    if (FUSE) {
        int h = blockIdx.x;
        float alv[16], arv[16];
#pragma unroll
        for (int nt = 0; nt < 8; nt++)
#pragma unroll
            for (int j = 0; j < 2; j++) {
                int cc = nt * 8 + (lane & 3) * 2 + j;
                alv[nt * 2 + j] = al[h * 64 + cc];
                arv[nt * 2 + j] = ar[h * 64 + cc];
            }
        float mel = -1e30f, mer = -1e30f;
#pragma unroll
        for (int mt = 0; mt < 2; mt++) {
            float e0 = 0, e1 = 0, f0 = 0, f1 = 0;
#pragma unroll
            for (int nt = 0; nt < 8; nt++)
#pragma unroll
                for (int j = 0; j < 2; j++) {
                    e0 += c[mt][nt][j]     * alv[nt * 2 + j];
                    e1 += c[mt][nt][2 + j] * alv[nt * 2 + j];
                    f0 += c[mt][nt][j]     * arv[nt * 2 + j];
                    f1 += c[mt][nt][2 + j] * arv[nt * 2 + j];
                }
#pragma unroll
            for (int off = 1; off < 4; off <<= 1) {
                e0 += __shfl_xor_sync(0xffffffffu, e0, off);
                e1 += __shfl_xor_sync(0xffffffffu, e1, off);
                f0 += __shfl_xor_sync(0xffffffffu, f0, off);
                f1 += __shfl_xor_sync(0xffffffffu, f1, off);
            }
            mel = fmaxf(mel, fmaxf(e0, e1));
            mer = fmaxf(mer, fmaxf(f0, f1));
            if ((lane & 3) == 0) {
                int r0 = rowBase + wid * 32 + mt * 16 + (lane >> 2);
                int r1 = r0 + 8;
                if (r0 < M) { el[(size_t)r0 * HH + h] = e0; er[(size_t)r0 * HH + h] = f0; }
                if (r1 < M) { el[(size_t)r1 * HH + h] = e1; er[(size_t)r1 * HH + h] = f1; }
            }
        }
        // warp max over row groups, then one atomic per warp per slot
#pragma unroll
        for (int off = 4; off < 32; off <<= 1) {
            mel = fmaxf(mel, __shfl_xor_sync(0xffffffffu, mel, off));
            mer = fmaxf(mer, __shfl_xor_sync(0xffffffffu, mer, off));
        }
        if (lane == 0) {
            atomicMax(&gmax[h],     enc_f(mel));
            atomicMax(&gmax[4 + h], enc_f(mer));
        }
    }
}

// ================= CSR build (once; edges shared by all layers) =================
__global__ void hist_k(const int* __restrict__ dst, int* deg, int E)
{
    int i = blockIdx.x * blockDim.x + threadIdx.x;
    if (i < E) atomicAdd(&deg[dst[i]], 1);
}

__global__ void scan_k(const int* __restrict__ deg, int* __restrict__ rowptr,
                       int* __restrict__ cursor, int n, int E)
{
    const int C = (n + 1023) >> 10;
    int t = threadIdx.x;
    int base = t * C;
    int s = 0;
    for (int i = 0; i < C; i++) { int id = base + i; if (id < n) s += deg[id]; }
    __shared__ int sm[1024];
    sm[t] = s;
    __syncthreads();
    for (int off = 1; off < 1024; off <<= 1) {
        int v = (t >= off) ? sm[t - off] : 0;
        __syncthreads();
        sm[t] += v;
        __syncthreads();
    }
    int run = sm[t] - s;
    for (int i = 0; i < C; i++) {
        int id = base + i;
        if (id < n) { rowptr[id] = run; cursor[id] = run; run += deg[id]; }
    }
    if (t == 0) rowptr[n] = E;
}

__global__ void scatter_k(const int* __restrict__ src, const int* __restrict__ dst,
                          int* cursor, int* __restrict__ esrc, int E)
{
    int i = blockIdx.x * blockDim.x + threadIdx.x;
    if (i >= E) return;
    int p = atomicAdd(&cursor[dst[i]], 1);
    esrc[p] = src[i];
}

// ================= GAT aggregation: 2 warps per node, 1 float4/lane (R7/R13) =================
template<int MODE>
__global__ void __launch_bounds__(256) gat_node_k(
    const float4* __restrict__ feat4,
    const int* __restrict__ rowptr, const int* __restrict__ esrc,
    const float* __restrict__ el, const float* __restrict__ er,
    const unsigned* __restrict__ gmax,
    const float4* __restrict__ res4, const float4* __restrict__ bias4,
    float* __restrict__ out)
{
    __shared__ float smv[4][64];
    int w    = threadIdx.x >> 5;
    int lane = threadIdx.x & 31;
    int gw   = blockIdx.x * 8 + w;
    int node = gw >> 1;
    int half = gw & 1;
    bool active = node < NN;

    float4 v = make_float4(0.f, 0.f, 0.f, 0.f);
    int colf = half * 32 + lane;
    int h    = colf >> 4;

    if (active) {
        int start = rowptr[node], end = rowptr[node + 1];
        float m   = dec_f(gmax[h]) + dec_f(gmax[4 + h]);
        float erB = er[(size_t)node * HH + h];

        float4 acc = make_float4(0.f, 0.f, 0.f, 0.f);
        float den = 0.f;
        int idx = start;
        for (; idx + 4 <= end; idx += 4) {
            int s0 = esrc[idx], s1 = esrc[idx + 1], s2 = esrc[idx + 2], s3 = esrc[idx + 3];
            float e0 = el[(size_t)s0 * HH + h];
            float e1 = el[(size_t)s1 * HH + h];
            float e2 = el[(size_t)s2 * HH + h];
            float e3 = el[(size_t)s3 * HH + h];
            float4 f0 = feat4[(size_t)s0 * 64 + colf];
            float4 f1 = feat4[(size_t)s1 * 64 + colf];
            float4 f2 = feat4[(size_t)s2 * 64 + colf];
            float4 f3 = feat4[(size_t)s3 * 64 + colf];
            float v0 = e0 + erB; v0 = v0 > 0.f ? v0 : 0.2f * v0;
            float v1 = e1 + erB; v1 = v1 > 0.f ? v1 : 0.2f * v1;
            float v2 = e2 + erB; v2 = v2 > 0.f ? v2 : 0.2f * v2;
            float v3 = e3 + erB; v3 = v3 > 0.f ? v3 : 0.2f * v3;
            float w0 = __expf(v0 - m), w1 = __expf(v1 - m);
            float w2 = __expf(v2 - m), w3 = __expf(v3 - m);
            den += (w0 + w1) + (w2 + w3);
            acc.x += w0 * f0.x + w1 * f1.x + w2 * f2.x + w3 * f3.x;
            acc.y += w0 * f0.y + w1 * f1.y + w2 * f2.y + w3 * f3.y;
            acc.z += w0 * f0.z + w1 * f1.z + w2 * f2.z + w3 * f3.z;
            acc.w += w0 * f0.w + w1 * f1.w + w2 * f2.w + w3 * f3.w;
        }
        for (; idx < end; idx++) {
            int s0 = esrc[idx];
            float e0 = el[(size_t)s0 * HH + h];
            float4 f0 = feat4[(size_t)s0 * 64 + colf];
            float v0 = e0 + erB; v0 = v0 > 0.f ? v0 : 0.2f * v0;
            float w0 = __expf(v0 - m);
            den += w0;
            acc.x += w0 * f0.x; acc.y += w0 * f0.y;
            acc.z += w0 * f0.z; acc.w += w0 * f0.w;
        }
        float inv = 1.f / fmaxf(den, 1e-16f);
        float4 r = res4[(size_t)node * 64 + colf];
        float4 b = bias4[colf];
        v.x = acc.x * inv + r.x + b.x;
        v.y = acc.y * inv + r.y + b.y;
        v.z = acc.z * inv + r.z + b.z;
        v.w = acc.w * inv + r.w + b.w;
    }

    if (MODE == 0) {
        if (active) {
            float4* o4 = (float4*)out + (size_t)node * 64 + colf;
            *o4 = make_float4(fmaxf(v.x, 0.f), fmaxf(v.y, 0.f), fmaxf(v.z, 0.f), fmaxf(v.w, 0.f));
        }
    } else {
        if (active) {
            v.x += __shfl_xor_sync(0xffffffffu, v.x, 16);
            v.y += __shfl_xor_sync(0xffffffffu, v.y, 16);
            v.z += __shfl_xor_sync(0xffffffffu, v.z, 16);
            v.w += __shfl_xor_sync(0xffffffffu, v.w, 16);
            if (half == 1 && lane < 16) *(float4*)&smv[w >> 1][lane * 4] = v;
        }
        __syncthreads();
        if (active && half == 0 && lane < 16) {
            float4 o = *(const float4*)&smv[w >> 1][lane * 4];
            float4 y = make_float4((v.x + o.x) * 0.25f, (v.y + o.y) * 0.25f,
                                   (v.z + o.z) * 0.25f, (v.w + o.w) * 0.25f);
            *((float4*)out + (size_t)node * 16 + lane) = y;
        }
    }
}

// ================= host orchestration (R13 multi-stream DAG; headmax fused) =================
extern "C" void kernel_launch(void* const* d_in, const int* in_sizes, int n_in,
                              void* d_out, int out_size)
{
    const float* x  = (const float*)d_in[0];
    const int*   ei = (const int*)d_in[1];
    const int E  = in_sizes[1] / 2;
    const int Nn = in_sizes[0] / FIN;
    const int* src = ei;
    const int* dst = ei + E;
    const float* W[3]  = {(const float*)d_in[2],  (const float*)d_in[3],  (const float*)d_in[4]};
    const float* al[3] = {(const float*)d_in[5],  (const float*)d_in[6],  (const float*)d_in[7]};
    const float* ar[3] = {(const float*)d_in[8],  (const float*)d_in[9],  (const float*)d_in[10]};
    const float* bb[3] = {(const float*)d_in[11], (const float*)d_in[12], (const float*)d_in[13]};
    const float* resW0 = (const float*)d_in[14];

    float *feat, *res, *h1, *h2, *el, *er;
    unsigned *gmax;
    unsigned *B0h, *B0l, *B1h, *B1l, *B2h, *B2l, *Brh, *Brl;
    int *deg, *rowptr, *cursor, *esrc;
    cudaGetSymbolAddress((void**)&feat,   g_feat);
    cudaGetSymbolAddress((void**)&res,    g_res);
    cudaGetSymbolAddress((void**)&h1,     g_h1);
    cudaGetSymbolAddress((void**)&h2,     g_h2);
    cudaGetSymbolAddress((void**)&el,     g_el);
    cudaGetSymbolAddress((void**)&er,     g_er);
    cudaGetSymbolAddress((void**)&gmax,   g_gmax);
    cudaGetSymbolAddress((void**)&B0h,    g_B0h);
    cudaGetSymbolAddress((void**)&B0l,    g_B0l);
    cudaGetSymbolAddress((void**)&B1h,    g_B1h);
    cudaGetSymbolAddress((void**)&B1l,    g_B1l);
    cudaGetSymbolAddress((void**)&B2h,    g_B2h);
    cudaGetSymbolAddress((void**)&B2l,    g_B2l);
    cudaGetSymbolAddress((void**)&Brh,    g_Brh);
    cudaGetSymbolAddress((void**)&Brl,    g_Brl);
    cudaGetSymbolAddress((void**)&deg,    g_deg);
    cudaGetSymbolAddress((void**)&rowptr, g_rowptr);
    cudaGetSymbolAddress((void**)&cursor, g_cursor);
    cudaGetSymbolAddress((void**)&esrc,   g_esrc);

    static cudaStream_t s1 = nullptr, s2 = nullptr, s3 = nullptr;
    static cudaEvent_t evRoot = nullptr, evCSR = nullptr, evRes = nullptr, evW12 = nullptr;
    if (!s1) {
        cudaStreamCreateWithFlags(&s1, cudaStreamNonBlocking);
        cudaStreamCreateWithFlags(&s2, cudaStreamNonBlocking);
        cudaStreamCreateWithFlags(&s3, cudaStreamNonBlocking);
        cudaEventCreateWithFlags(&evRoot, cudaEventDisableTiming);
        cudaEventCreateWithFlags(&evCSR,  cudaEventDisableTiming);
        cudaEventCreateWithFlags(&evRes,  cudaEventDisableTiming);
        cudaEventCreateWithFlags(&evW12,  cudaEventDisableTiming);
    }

    const dim3 gemmGrid(HID / BN, (Nn + BM - 1) / BM);
    const int nodeGrid = (2 * Nn + 7) / 8;

    // ---- root: clear per-layer gmax slots + degree histogram; fork ----
    cudaMemsetAsync(gmax, 0, 24 * sizeof(unsigned), 0);
    cudaMemsetAsync(deg, 0, (size_t)Nn * sizeof(int), 0);
    cudaEventRecord(evRoot, 0);

    // ---- s1: CSR chain (independent of GEMMs) ----
    cudaStreamWaitEvent(s1, evRoot, 0);
    hist_k<<<(E + 255) / 256, 256, 0, s1>>>(dst, deg, E);
    scan_k<<<1, 1024, 0, s1>>>(deg, rowptr, cursor, Nn, E);
    scatter_k<<<(E + 255) / 256, 256, 0, s1>>>(src, dst, cursor, esrc, E);
    cudaEventRecord(evCSR, s1);

    // ---- s2: residual projection path ----
    cudaStreamWaitEvent(s2, evRoot, 0);
    convW_k<<<(FIN / 2 * HID + 255) / 256, 256, 0, s2>>>(resW0, Brh, Brl, FIN / 2, HID);
    gemm_bf16x3<false><<<gemmGrid, 128, 0, s2>>>(x, Brh, Brl, res,
        nullptr, nullptr, nullptr, nullptr, nullptr, Nn, FIN, HID);
    cudaEventRecord(evRes, s2);

    // ---- s3: W1/W2 conversions ----
    cudaStreamWaitEvent(s3, evRoot, 0);
    convW_k<<<(HID / 2 * HID + 255) / 256, 256, 0, s3>>>(W[1], B1h, B1l, HID / 2, HID);
    convW_k<<<(HID / 2 * HID + 255) / 256, 256, 0, s3>>>(W[2], B2h, B2l, HID / 2, HID);
    cudaEventRecord(evW12, s3);

    // ---- main chain (stream 0) ----
    // Layer 0
    convW_k<<<(FIN / 2 * HID + 255) / 256, 256>>>(W[0], B0h, B0l, FIN / 2, HID);
    gemm_bf16x3<true><<<gemmGrid, 128>>>(x, B0h, B0l, feat,
        al[0], ar[0], el, er, gmax + 0, Nn, FIN, HID);
    cudaStreamWaitEvent(0, evCSR, 0);
    cudaStreamWaitEvent(0, evRes, 0);
    gat_node_k<0><<<nodeGrid, 256>>>((const float4*)feat, rowptr, esrc, el, er, gmax + 0,
                                     (const float4*)res, (const float4*)bb[0], h1);

    // Layer 1
    cudaStreamWaitEvent(0, evW12, 0);
    gemm_bf16x3<true><<<gemmGrid, 128>>>(h1, B1h, B1l, feat,
        al[1], ar[1], el, er, gmax + 8, Nn, HID, HID);
    gat_node_k<0><<<nodeGrid, 256>>>((const float4*)feat, rowptr, esrc, el, er, gmax + 8,
                                     (const float4*)h1, (const float4*)bb[1], h2);

    // Layer 2
    gemm_bf16x3<true><<<gemmGrid, 128>>>(h2, B2h, B2l, feat,
        al[2], ar[2], el, er, gmax + 16, Nn, HID, HID);
    gat_node_k<2><<<nodeGrid, 256>>>((const float4*)feat, rowptr, esrc, el, er, gmax + 16,
                                     (const float4*)h2, (const float4*)bb[2], (float*)d_out);
}